// round 1
// baseline (speedup 1.0000x reference)
#include <cuda_runtime.h>
#include <cuda_bf16.h>
#include <cstddef>

// CCLayer: D=256, P=32, N=262144
//   Z  = ZPi[0:256, :],  Pi = ZPi[256:288, :]
//   UtZ = U^T Z                       (P x N)
//   s   = sum_p Pi[p, :]              (N)
//   w   = (alpha - UtZ) * Pi          (P x N)   [folds the two U@ terms]
//   Zout= Z * s + U @ w               (D x N)
//   out = vstack(Zout, Pi)
//
// Round 1: SIMT fp32 baseline. One column per thread; U + alpha in smem;
// pass A accumulates UtZ, pass B re-reads Z (L2-resident) and writes output.

#define DD 256
#define PP 32

__global__ __launch_bounds__(256, 2)
void cclayer_kernel(const float* __restrict__ ZPi,
                    const float* __restrict__ U,
                    const float* __restrict__ alpha,
                    float* __restrict__ out,
                    int N) {
    __shared__ float sU[DD * PP];   // 32 KB, row-major U[d][p]
    __shared__ float sAlpha[PP];

    const int tid = threadIdx.x;
    for (int i = tid; i < DD * PP; i += blockDim.x) sU[i] = U[i];
    if (tid < PP) sAlpha[tid] = alpha[tid];
    __syncthreads();

    const int col = blockIdx.x * blockDim.x + tid;
    if (col >= N) return;  // no further barriers below

    const float* __restrict__ zcol = ZPi + col;
    const size_t sN = (size_t)N;

    // ---- load Pi column, compute s ----
    float pi[PP];
    float s = 0.f;
#pragma unroll
    for (int p = 0; p < PP; p++) {
        pi[p] = zcol[(size_t)(DD + p) * sN];
        s += pi[p];
    }

    // ---- pass A: utz[p] = sum_d U[d][p] * z[d] ----
    float utz[PP];
#pragma unroll
    for (int p = 0; p < PP; p++) utz[p] = 0.f;

#pragma unroll 4
    for (int d = 0; d < DD; d++) {
        const float z = zcol[(size_t)d * sN];
        const float4* __restrict__ urow = (const float4*)(sU + d * PP);
#pragma unroll
        for (int q = 0; q < PP / 4; q++) {
            const float4 u = urow[q];
            utz[4 * q + 0] = fmaf(u.x, z, utz[4 * q + 0]);
            utz[4 * q + 1] = fmaf(u.y, z, utz[4 * q + 1]);
            utz[4 * q + 2] = fmaf(u.z, z, utz[4 * q + 2]);
            utz[4 * q + 3] = fmaf(u.w, z, utz[4 * q + 3]);
        }
    }

    // ---- w[p] = (alpha[p] - utz[p]) * pi[p]  (reuse utz storage) ----
#pragma unroll
    for (int p = 0; p < PP; p++) utz[p] = (sAlpha[p] - utz[p]) * pi[p];

    // ---- pass B: out[d] = z[d]*s + sum_p U[d][p]*w[p]  (Z reload hits L2) ----
#pragma unroll 2
    for (int d = 0; d < DD; d++) {
        const float z = zcol[(size_t)d * sN];
        const float4* __restrict__ urow = (const float4*)(sU + d * PP);
        float acc0 = 0.f, acc1 = 0.f;
#pragma unroll
        for (int q = 0; q < PP / 4; q += 2) {
            const float4 ua = urow[q];
            const float4 ub = urow[q + 1];
            acc0 = fmaf(ua.x, utz[4 * q + 0], acc0);
            acc1 = fmaf(ua.y, utz[4 * q + 1], acc1);
            acc0 = fmaf(ua.z, utz[4 * q + 2], acc0);
            acc1 = fmaf(ua.w, utz[4 * q + 3], acc1);
            acc0 = fmaf(ub.x, utz[4 * q + 4], acc0);
            acc1 = fmaf(ub.y, utz[4 * q + 5], acc1);
            acc0 = fmaf(ub.z, utz[4 * q + 6], acc0);
            acc1 = fmaf(ub.w, utz[4 * q + 7], acc1);
        }
        out[(size_t)d * sN + col] = fmaf(z, s, acc0 + acc1);
    }

    // ---- Pi pass-through ----
#pragma unroll
    for (int p = 0; p < PP; p++) {
        out[(size_t)(DD + p) * sN + col] = pi[p];
    }
}

extern "C" void kernel_launch(void* const* d_in, const int* in_sizes, int n_in,
                              void* d_out, int out_size) {
    const float* ZPi   = (const float*)d_in[0];
    const float* U     = (const float*)d_in[1];
    const float* alpha = (const float*)d_in[2];
    float* out = (float*)d_out;

    const int N = in_sizes[0] / (DD + PP);   // 288 rows total

    const int threads = 256;
    const int blocks = (N + threads - 1) / threads;
    cclayer_kernel<<<blocks, threads>>>(ZPi, U, alpha, out, N);
}

// round 2
// speedup vs baseline: 1.2243x; 1.2243x over previous
#include <cuda_runtime.h>
#include <cuda_bf16.h>
#include <cstdint>
#include <cstddef>

// CCLayer: D=256, P=32, N=262144
//   Z  = ZPi[0:256, :],  Pi = ZPi[256:288, :]
//   UtZ = U^T Z ; s = sum_p Pi ; w = (alpha - UtZ) .* Pi
//   out[0:256]   = Z * s + U @ w
//   out[256:288] = Pi
//
// Round 2: packed f32x2 math (fma.rn.f32x2 — PTX-only on sm_103a),
// accumulators packed over p-pairs so U rows feed 64-bit operands directly
// from shared memory. Occupancy raised via launch_bounds(256,3) and by not
// keeping Pi resident in registers.

#define DD 256
#define PP 32

#define FMA2(acc, a, b) \
    asm("fma.rn.f32x2 %0, %1, %2, %0;" : "+l"(acc) : "l"(a), "l"(b))
#define PACK2(d, lo, hi) \
    asm("mov.b64 %0, {%1, %2};" : "=l"(d) : "f"(lo), "f"(hi))
#define UNPACK2(lo, hi, d) \
    asm("mov.b64 {%0, %1}, %2;" : "=f"(lo), "=f"(hi) : "l"(d))
#define LDS_2X64(a, b, addr) \
    asm("ld.shared.v2.u64 {%0, %1}, [%2];" : "=l"(a), "=l"(b) : "r"(addr))

__global__ __launch_bounds__(256, 3)
void cclayer_kernel(const float* __restrict__ ZPi,
                    const float* __restrict__ U,
                    const float* __restrict__ alpha,
                    float* __restrict__ out,
                    int N) {
    __shared__ __align__(16) float sU[DD * PP];   // 32 KB, row-major U[d][p]
    __shared__ float sAlpha[PP];

    const int tid = threadIdx.x;
    for (int i = tid; i < DD * PP; i += blockDim.x) sU[i] = U[i];
    if (tid < PP) sAlpha[tid] = alpha[tid];
    __syncthreads();

    const int col = blockIdx.x * blockDim.x + tid;
    if (col >= N) return;  // no barriers below

    uint32_t su_base;
    asm("{ .reg .u64 t; cvta.to.shared.u64 t, %1; cvt.u32.u64 %0, t; }"
        : "=r"(su_base) : "l"(sU));

    const size_t sN = (size_t)N;
    const float* __restrict__ zc = ZPi + col;
    float* __restrict__ oc = out + col;

    // ---- Pi pass-through + s (don't keep pi in regs) ----
    float s = 0.f;
#pragma unroll
    for (int p = 0; p < PP; p++) {
        const float v = zc[(size_t)(DD + p) * sN];
        s += v;
        oc[(size_t)(DD + p) * sN] = v;
    }

    // ---- pass A: utz2[q] = sum_d (u[d][2q], u[d][2q+1]) * (z,z) ----
    unsigned long long acc[PP / 2];
#pragma unroll
    for (int q = 0; q < PP / 2; q++) acc[q] = 0ULL;  // (0.f, 0.f)

#pragma unroll 4
    for (int d = 0; d < DD; d++) {
        const float z = zc[(size_t)d * sN];
        unsigned long long z2;
        PACK2(z2, z, z);
        const uint32_t rowa = su_base + d * (PP * 4);
#pragma unroll
        for (int i = 0; i < 8; i++) {
            unsigned long long u0, u1;
            LDS_2X64(u0, u1, rowa + i * 16);
            FMA2(acc[2 * i], u0, z2);
            FMA2(acc[2 * i + 1], u1, z2);
        }
    }

    // ---- w2[q] = (alpha - utz) .* pi  (Pi reloaded; L2-resident or cheap) ----
#pragma unroll
    for (int q = 0; q < PP / 2; q++) {
        float a0, a1;
        UNPACK2(a0, a1, acc[q]);
        const float p0 = zc[(size_t)(DD + 2 * q) * sN];
        const float p1 = zc[(size_t)(DD + 2 * q + 1) * sN];
        const float w0 = (sAlpha[2 * q] - a0) * p0;
        const float w1 = (sAlpha[2 * q + 1] - a1) * p1;
        PACK2(acc[q], w0, w1);
    }

    // ---- pass B: out[d] = z*s + sum_q dot2(u2[d][q], w2[q]) ----
#pragma unroll 2
    for (int d = 0; d < DD; d++) {
        const float z = zc[(size_t)d * sN];
        const uint32_t rowa = su_base + d * (PP * 4);
        unsigned long long r0 = 0ULL, r1 = 0ULL;
#pragma unroll
        for (int i = 0; i < 8; i++) {
            unsigned long long u0, u1;
            LDS_2X64(u0, u1, rowa + i * 16);
            FMA2(r0, u0, acc[2 * i]);
            FMA2(r1, u1, acc[2 * i + 1]);
        }
        float x0, x1, y0, y1;
        UNPACK2(x0, x1, r0);
        UNPACK2(y0, y1, r1);
        oc[(size_t)d * sN] = fmaf(z, s, (x0 + x1) + (y0 + y1));
    }
}

extern "C" void kernel_launch(void* const* d_in, const int* in_sizes, int n_in,
                              void* d_out, int out_size) {
    const float* ZPi   = (const float*)d_in[0];
    const float* U     = (const float*)d_in[1];
    const float* alpha = (const float*)d_in[2];
    float* out = (float*)d_out;

    const int N = in_sizes[0] / (DD + PP);   // 288 rows total

    const int threads = 256;
    const int blocks = (N + threads - 1) / threads;
    cclayer_kernel<<<blocks, threads>>>(ZPi, U, alpha, out, N);
}

// round 4
// speedup vs baseline: 1.2391x; 1.0121x over previous
#include <cuda_runtime.h>
#include <cuda_bf16.h>
#include <cstdint>
#include <cstddef>

// CCLayer via mma.sync (HMMA bf16, hi/lo split x3 for fp32-grade accuracy).
//   D1[j,p]  = Z_tile^T @ U          (m=cols j, n=p, k=d)
//   w = (alpha - D1) .* Pi ; s = colsum(Pi); Pi pass-through
//   D2[j,d]  = w @ U^T               (m=cols j, n=d, k=p)
//   out = z*s + D2
#define DD 256
#define PP 32
#define TILE 128

#define A_STR  272   // [d][j] bf16 rows: 128*2 + 16 pad (acts as swizzle)
#define U1_STR 528   // [p][d] bf16 rows: 256*2 + 16 pad
#define U2_STR 80    // [d][p] bf16 rows: 32*2 + 16 pad
#define W_STR  80    // [j][p] bf16 rows
#define S2_STR 528   // [dloc][j] f32 rows: 128*4 + 16 pad

#define OFF_A_HI  0          // 256*272 = 69632
#define OFF_A_LO  69632
#define OFF_U1H   139264     // 32*528 = 16896
#define OFF_U1L   156160
#define OFF_U2H   173056     // 256*80 = 20480
#define OFF_U2L   193536
#define OFF_SPART 214016     // 256 f32
#define OFF_SARR  215040     // 128 f32
#define OFF_ALPHA 215552     // 32 f32
#define SMEM_BYTES 215680

// aliases inside the (dead-after-GEMM1) A region
#define OFF_W_HI  (OFF_A_HI)            // 128*80 = 10240
#define OFF_W_LO  (OFF_A_HI + 10240)
#define OFF_S2    (OFF_A_HI + 24576)    // 128*528 = 67584 (ends 92160 < 139264)

#define MMA_BF16(d, a0, a1, a2, a3, b0, b1)                                  \
    asm volatile(                                                            \
        "mma.sync.aligned.m16n8k16.row.col.f32.bf16.bf16.f32 "               \
        "{%0,%1,%2,%3}, {%4,%5,%6,%7}, {%8,%9}, {%0,%1,%2,%3};"              \
        : "+f"(d[0]), "+f"(d[1]), "+f"(d[2]), "+f"(d[3])                     \
        : "r"(a0), "r"(a1), "r"(a2), "r"(a3), "r"(b0), "r"(b1))

#define LDSM_T4(r0, r1, r2, r3, addr)                                        \
    asm volatile(                                                            \
        "ldmatrix.sync.aligned.m8n8.x4.trans.shared.b16 {%0,%1,%2,%3}, [%4];"\
        : "=r"(r0), "=r"(r1), "=r"(r2), "=r"(r3) : "r"(addr))

#define LDS32(r, addr) \
    asm volatile("ld.shared.b32 %0, [%1];" : "=r"(r) : "r"(addr))
#define STS32(addr, v) \
    asm volatile("st.shared.b32 [%0], %1;" :: "r"(addr), "r"(v) : "memory")

__device__ __forceinline__ uint32_t pack_hi2(float a, float b) {
    __nv_bfloat16 ha = __float2bfloat16_rn(a);
    __nv_bfloat16 hb = __float2bfloat16_rn(b);
    return (uint32_t)__bfloat16_as_ushort(ha) |
           ((uint32_t)__bfloat16_as_ushort(hb) << 16);
}
__device__ __forceinline__ uint32_t pack_lo2(float a, float b) {
    __nv_bfloat16 ha = __float2bfloat16_rn(a);
    __nv_bfloat16 hb = __float2bfloat16_rn(b);
    float ra = a - __bfloat162float(ha);
    float rb = b - __bfloat162float(hb);
    return (uint32_t)__bfloat16_as_ushort(__float2bfloat16_rn(ra)) |
           ((uint32_t)__bfloat16_as_ushort(__float2bfloat16_rn(rb)) << 16);
}

__global__ __launch_bounds__(256, 1)
void cclayer_mma(const float* __restrict__ ZPi,
                 const float* __restrict__ U,
                 const float* __restrict__ alpha,
                 float* __restrict__ out,
                 int N, int ntiles) {
    extern __shared__ __align__(128) char smem[];
    uint32_t sbase;
    asm("{ .reg .u64 t; cvta.to.shared.u64 t, %1; cvt.u32.u64 %0, t; }"
        : "=r"(sbase) : "l"(smem));

    const int tid = threadIdx.x;
    const int warp = tid >> 5;
    const int lane = tid & 31;
    const int j0 = warp * 16;            // warp's column rows (m)
    const size_t sN = (size_t)N;

    // ---- persistent U staging: U1[p][d], U2[d][p], hi/lo ----
    for (int i = tid; i < DD * PP; i += 256) {
        const int d = i >> 5, p = i & 31;
        const float v = U[i];
        const __nv_bfloat16 h = __float2bfloat16_rn(v);
        const __nv_bfloat16 l = __float2bfloat16_rn(v - __bfloat162float(h));
        *(uint16_t*)(smem + OFF_U1H + p * U1_STR + d * 2) = __bfloat16_as_ushort(h);
        *(uint16_t*)(smem + OFF_U1L + p * U1_STR + d * 2) = __bfloat16_as_ushort(l);
        *(uint16_t*)(smem + OFF_U2H + d * U2_STR + p * 2) = __bfloat16_as_ushort(h);
        *(uint16_t*)(smem + OFF_U2L + d * U2_STR + p * 2) = __bfloat16_as_ushort(l);
    }
    if (tid < PP) ((float*)(smem + OFF_ALPHA))[tid] = alpha[tid];
    __syncthreads();

    const float* __restrict__ sAlpha = (const float*)(smem + OFF_ALPHA);
    float* __restrict__ sPart = (float*)(smem + OFF_SPART);
    float* __restrict__ sArr = (float*)(smem + OFF_SARR);

    // lane decode for ldmatrix.x4.trans A-fragment addressing ([k][m] source)
    const int krow = (lane & 7) + ((lane >> 4) & 1) * 8;
    const int jcolb = (j0 + ((lane >> 3) & 1) * 8) * 2;
    const uint32_t aHiBase = sbase + OFF_A_HI + krow * A_STR + jcolb;
    const uint32_t aLoBase = sbase + OFF_A_LO + krow * A_STR + jcolb;
    // GEMM1 B base: p = lane/4, dbyte = (lane%4)*4
    const uint32_t b1off = (uint32_t)((lane >> 2) * U1_STR + (lane & 3) * 4);
    // GEMM2 B base: dout = lane/4, pbyte = (lane%4)*4
    const uint32_t b2off = (uint32_t)((lane >> 2) * U2_STR + (lane & 3) * 4);
    // GEMM2 A (w) base: j = j0 + lane/4, pbyte = (lane%4)*4
    const uint32_t wOff = (uint32_t)((j0 + (lane >> 2)) * W_STR + (lane & 3) * 4);

    for (int t = blockIdx.x; t < ntiles; t += gridDim.x) {
        const int col0 = t * TILE;

        // ================= phase 1: Pi pass-through + s, A fill =========
        {
            const int j = tid & 127;
            const int pb = tid >> 7;
            float sp = 0.f;
#pragma unroll
            for (int i = 0; i < 16; i++) {
                const int p = pb + 2 * i;
                const size_t off = (size_t)(DD + p) * sN + col0 + j;
                const float v = ZPi[off];
                out[off] = v;
                sp += v;
            }
            sPart[tid] = sp;
        }
#pragma unroll 4
        for (int it = 0; it < 64; it++) {
            const int task = it * 8 + warp;
            const int d = task >> 1, half = task & 1;
            const float2 v = *(const float2*)(ZPi + (size_t)d * sN + col0 +
                                              half * 64 + 2 * lane);
            const uint32_t soff = d * A_STR + half * 128 + lane * 4;
            *(uint32_t*)(smem + OFF_A_HI + soff) = pack_hi2(v.x, v.y);
            *(uint32_t*)(smem + OFF_A_LO + soff) = pack_lo2(v.x, v.y);
        }
        __syncthreads();
        if (tid < 128) sArr[tid] = sPart[tid] + sPart[tid + 128];

        // ================= GEMM1: D1[16j x 32p], k = 256 ================
        float d1[4][4];
#pragma unroll
        for (int nt = 0; nt < 4; nt++)
#pragma unroll
            for (int q = 0; q < 4; q++) d1[nt][q] = 0.f;

        for (int ks = 0; ks < 16; ks++) {
            uint32_t ah0, ah1, ah2, ah3, al0, al1, al2, al3;
            LDSM_T4(ah0, ah1, ah2, ah3, aHiBase + ks * 16 * A_STR);
            LDSM_T4(al0, al1, al2, al3, aLoBase + ks * 16 * A_STR);
            const uint32_t bh_base = sbase + OFF_U1H + b1off + ks * 32;
            const uint32_t bl_base = sbase + OFF_U1L + b1off + ks * 32;
#pragma unroll
            for (int nt = 0; nt < 4; nt++) {
                uint32_t bh0, bh1, bl0, bl1;
                LDS32(bh0, bh_base + nt * 8 * U1_STR);
                LDS32(bh1, bh_base + nt * 8 * U1_STR + 16);
                LDS32(bl0, bl_base + nt * 8 * U1_STR);
                LDS32(bl1, bl_base + nt * 8 * U1_STR + 16);
                MMA_BF16(d1[nt], ah0, ah1, ah2, ah3, bh0, bh1);
                MMA_BF16(d1[nt], ah0, ah1, ah2, ah3, bl0, bl1);
                MMA_BF16(d1[nt], al0, al1, al2, al3, bh0, bh1);
            }
        }
        __syncthreads();   // all A reads done before w/S2 alias writes

        // ================= epilogue 1: w = (alpha - D1) .* Pi ===========
        {
            const int cj = col0 + j0 + (lane >> 2);
#pragma unroll
            for (int nt = 0; nt < 4; nt++) {
                const int p0 = nt * 8 + 2 * (lane & 3);
                const float a0 = sAlpha[p0], a1 = sAlpha[p0 + 1];
                const float pi00 = ZPi[(size_t)(DD + p0) * sN + cj];
                const float pi10 = ZPi[(size_t)(DD + p0 + 1) * sN + cj];
                const float pi01 = ZPi[(size_t)(DD + p0) * sN + cj + 8];
                const float pi11 = ZPi[(size_t)(DD + p0 + 1) * sN + cj + 8];
                const float w0 = (a0 - d1[nt][0]) * pi00;
                const float w1 = (a1 - d1[nt][1]) * pi10;
                const float w2 = (a0 - d1[nt][2]) * pi01;
                const float w3 = (a1 - d1[nt][3]) * pi11;
                const uint32_t wa = sbase + (uint32_t)((j0 + (lane >> 2)) * W_STR + p0 * 2);
                STS32(wa + OFF_W_HI, pack_hi2(w0, w1));
                STS32(wa + OFF_W_LO, pack_lo2(w0, w1));
                STS32(wa + OFF_W_HI + 8 * W_STR, pack_hi2(w2, w3));
                STS32(wa + OFF_W_LO + 8 * W_STR, pack_lo2(w2, w3));
            }
        }
        __syncwarp();

        // ================= GEMM2 (two halves of 128 d each) =============
#pragma unroll 1
        for (int h = 0; h < 2; h++) {
            float d2[16][4];
#pragma unroll
            for (int nt = 0; nt < 16; nt++)
#pragma unroll
                for (int q = 0; q < 4; q++) d2[nt][q] = 0.f;

#pragma unroll
            for (int ks = 0; ks < 2; ks++) {
                uint32_t ah0, ah1, ah2, ah3, al0, al1, al2, al3;
                const uint32_t wh = sbase + OFF_W_HI + wOff + ks * 32;
                const uint32_t wl = sbase + OFF_W_LO + wOff + ks * 32;
                LDS32(ah0, wh);
                LDS32(ah1, wh + 8 * W_STR);
                LDS32(ah2, wh + 16);
                LDS32(ah3, wh + 8 * W_STR + 16);
                LDS32(al0, wl);
                LDS32(al1, wl + 8 * W_STR);
                LDS32(al2, wl + 16);
                LDS32(al3, wl + 8 * W_STR + 16);
                const uint32_t bh_base = sbase + OFF_U2H + b2off +
                                         (h * 128) * U2_STR + ks * 32;
                const uint32_t bl_base = sbase + OFF_U2L + b2off +
                                         (h * 128) * U2_STR + ks * 32;
#pragma unroll
                for (int nt = 0; nt < 16; nt++) {
                    uint32_t bh0, bh1, bl0, bl1;
                    LDS32(bh0, bh_base + nt * 8 * U2_STR);
                    LDS32(bh1, bh_base + nt * 8 * U2_STR + 16);
                    LDS32(bl0, bl_base + nt * 8 * U2_STR);
                    LDS32(bl1, bl_base + nt * 8 * U2_STR + 16);
                    MMA_BF16(d2[nt], ah0, ah1, ah2, ah3, bh0, bh1);
                    MMA_BF16(d2[nt], ah0, ah1, ah2, ah3, bl0, bl1);
                    MMA_BF16(d2[nt], al0, al1, al2, al3, bh0, bh1);
                }
            }

            // stage D2 fragments into S2 [dloc][j]
#pragma unroll
            for (int nt = 0; nt < 16; nt++) {
                const int r = nt * 8 + 2 * (lane & 3);
                const uint32_t a = sbase + OFF_S2 +
                                   (uint32_t)(r * S2_STR + (j0 + (lane >> 2)) * 4);
                STS32(a, __float_as_uint(d2[nt][0]));
                STS32(a + S2_STR, __float_as_uint(d2[nt][1]));
                STS32(a + 32, __float_as_uint(d2[nt][2]));
                STS32(a + S2_STR + 32, __float_as_uint(d2[nt][3]));
            }
            __syncthreads();

            // coalesced flush: out = z*s + D2
            {
                const int j = tid & 127;
                const int rh = tid >> 7;
                const float sj = sArr[j];
#pragma unroll 4
                for (int i = 0; i < 64; i++) {
                    const int r = i * 2 + rh;
                    const float v = *(const float*)(smem + OFF_S2 + r * S2_STR + j * 4);
                    const size_t off = (size_t)(h * 128 + r) * sN + col0 + j;
                    out[off] = fmaf(ZPi[off], sj, v);
                }
            }
            __syncthreads();
        }
    }
}

extern "C" void kernel_launch(void* const* d_in, const int* in_sizes, int n_in,
                              void* d_out, int out_size) {
    const float* ZPi   = (const float*)d_in[0];
    const float* U     = (const float*)d_in[1];
    const float* alpha = (const float*)d_in[2];
    float* out = (float*)d_out;

    const int N = in_sizes[0] / (DD + PP);
    const int ntiles = N / TILE;

    static int nsm = 0;
    if (nsm == 0) {
        cudaDeviceGetAttribute(&nsm, cudaDevAttrMultiProcessorCount, 0);
        cudaFuncSetAttribute(cclayer_mma, cudaFuncAttributeMaxDynamicSharedMemorySize,
                             SMEM_BYTES);
    }
    const int grid = nsm < ntiles ? nsm : ntiles;
    cclayer_mma<<<grid, 256, SMEM_BYTES>>>(ZPi, U, alpha, out, N, ntiles);
}